// round 2
// baseline (speedup 1.0000x reference)
#include <cuda_runtime.h>
#include <math.h>
#include <stdint.h>

#define TT   1536
#define CDIM 1536
#define HH   8
#define KD   64
#define VD   192
#define RD   3071   // 2T-1
#define NB   32

// ---------------- scratch (static device globals; allocation-free) ----------------
__device__ float g_posenc[RD * 192];
__device__ float g_gprobs[RD * NB];
__device__ float g_gmax;
__device__ float g_rk[HH * RD * KD];
__device__ float g_q [HH * TT * KD];
__device__ float g_qw[HH * TT * KD];
__device__ float g_qr[HH * TT * KD];
__device__ float g_k [HH * TT * KD];
__device__ float g_v [HH * TT * VD];
__device__ float g_logits[(size_t)HH * TT * TT];
__device__ float g_attn[TT * (HH * VD)];

// ---------------- positional features ----------------

// gamma pdf, computed in double to avoid fp32 cancellation (lgamma ~3e4 at conc=4096)
__global__ void pf_gamma_raw_kernel() {
    int idx = blockIdx.x * blockDim.x + threadIdx.x;
    if (idx >= RD * NB) return;
    int r = idx / NB, i = idx % NB;
    double x    = fabs((double)(r - (TT - 1)));
    double mean = 48.0 * (i + 1);                 // linspace(48,1536,32), step exactly 48
    double conc = (mean / 24.0) * (mean / 24.0);
    double rate = mean / 576.0;
    double lu   = (conc - 1.0) * log(x) - rate * x;   // x==0 -> -inf -> exp()=0 (matches xlogy)
    double ln   = lgamma(conc) - conc * log(rate);
    double p    = exp(lu - ln);
    g_gprobs[idx] = (float)p + 1e-8f;
}

__global__ void pf_max_kernel() {
    __shared__ float s[1024];
    int t = threadIdx.x;
    float m = 0.f;
    for (int i = t; i < RD * NB; i += 1024) m = fmaxf(m, g_gprobs[i]);
    s[t] = m; __syncthreads();
    for (int o = 512; o > 0; o >>= 1) { if (t < o) s[t] = fmaxf(s[t], s[t + o]); __syncthreads(); }
    if (t == 0) g_gmax = s[0];
}

__global__ void pf_build_kernel() {
    int idx = blockIdx.x * blockDim.x + threadIdx.x;
    if (idx >= RD * 96) return;
    int r = idx / 96, i = idx % 96;
    float p  = (float)(r - (TT - 1));
    float ap = fabsf(p);
    float val;
    if (i < 32) {
        double mr = log(1536.0) / log(2.0);
        double hl = pow(2.0, 3.0 + (double)i * (mr - 3.0) / 31.0);
        val = expf(-(float)(0.6931471805599453 / hl) * ap);
    } else if (i < 64) {
        float cw = exp2f((float)(i - 32 + 1)) - 1.0f;
        val = (cw > ap) ? 1.0f : 0.0f;
    } else {
        val = g_gprobs[r * NB + (i - 64)] / g_gmax;
    }
    float sg = (p > 0.f) ? 1.f : ((p < 0.f) ? -1.f : 0.f);
    g_posenc[r * 192 + i]      = val;
    g_posenc[r * 192 + 96 + i] = sg * val;
}

// ---------------- generic batched SGEMM: C = alpha * A@B (+bias), opt head-major C ----------------
// A row-major [M,Kd] (lda), B row-major [Kd,N] (ldb).
// hd==0: C[z*sC + m*ldc + n]; hd>0: C[((n/hd)*M + m)*hd + n%hd]  (head-major, batch=1)
__global__ void sgemm_kernel(const float* __restrict__ A, int lda, size_t sA,
                             const float* __restrict__ B, int ldb, size_t sB,
                             float* __restrict__ C, int ldc, size_t sC,
                             int M, int N, int Kd, float alpha,
                             const float* __restrict__ bias, int hd) {
    __shared__ float As[16][68];
    __shared__ float Bs[16][68];
    int z = blockIdx.z;
    A += (size_t)z * sA;  B += (size_t)z * sB;
    size_t coff = (size_t)z * sC;
    int n0 = blockIdx.x * 64, m0 = blockIdx.y * 64;
    int tx = threadIdx.x, ty = threadIdx.y, tid = ty * 16 + tx;
    float acc[4][4] = {};
    for (int kc = 0; kc < Kd; kc += 16) {
        #pragma unroll
        for (int t = 0; t < 4; t++) {
            int e = tid + t * 256;
            int m = e >> 4, kk = e & 15;
            float v = 0.f;
            if (m0 + m < M) v = A[(size_t)(m0 + m) * lda + kc + kk];
            As[kk][m] = v;
        }
        #pragma unroll
        for (int t = 0; t < 4; t++) {
            int e = tid + t * 256;
            int kk = e >> 6, n = e & 63;
            Bs[kk][n] = B[(size_t)(kc + kk) * ldb + n0 + n];
        }
        __syncthreads();
        #pragma unroll
        for (int kk = 0; kk < 16; kk++) {
            float a[4], b[4];
            #pragma unroll
            for (int i = 0; i < 4; i++) a[i] = As[kk][ty * 4 + i];
            #pragma unroll
            for (int j = 0; j < 4; j++) b[j] = Bs[kk][tx * 4 + j];
            #pragma unroll
            for (int i = 0; i < 4; i++)
                #pragma unroll
                for (int j = 0; j < 4; j++)
                    acc[i][j] += a[i] * b[j];
        }
        __syncthreads();
    }
    #pragma unroll
    for (int i = 0; i < 4; i++) {
        int m = m0 + ty * 4 + i;
        if (m >= M) break;
        #pragma unroll
        for (int j = 0; j < 4; j++) {
            int n = n0 + tx * 4 + j;
            float v = alpha * acc[i][j];
            if (bias) v += bias[n];
            size_t idx;
            if (hd) idx = ((size_t)(n / hd) * M + m) * (size_t)hd + (n % hd);
            else    idx = coff + (size_t)m * ldc + n;
            C[idx] = v;
        }
    }
}

// ---------------- qw/qr = q + biases ----------------
__global__ void qbias_kernel(const float* __restrict__ rwb, const float* __restrict__ rrb) {
    int idx = blockIdx.x * blockDim.x + threadIdx.x;
    if (idx >= HH * TT * KD) return;
    int h = idx / (TT * KD);
    int d = idx & (KD - 1);
    float q = g_q[idx];
    g_qw[idx] = q + rwb[h * KD + d];
    g_qr[idx] = q + rrb[h * KD + d];
}

// ---------------- fused content + relative logits (analytic relative_shift) ----------------
// logits[h,q,j] = (q+rwb)[h,q]·k[h,j] + (q+rrb)[h,q]·r_k[h, j-q+T-1]
__global__ void logits_kernel() {
    __shared__ float qws[16][68], qrs[16][68], ks[16][68], rks[16][132];
    int h  = blockIdx.z;
    int q0 = blockIdx.y * 64, j0 = blockIdx.x * 64;
    int tx = threadIdx.x, ty = threadIdx.y, tid = ty * 16 + tx;
    int rbase = j0 - q0 + (TT - 64);   // r = rbase + (n - m + 63), always in [0,3070]
    const float* qwp = g_qw + (size_t)h * TT * KD;
    const float* qrp = g_qr + (size_t)h * TT * KD;
    const float* kp  = g_k  + (size_t)h * TT * KD;
    const float* rkp = g_rk + (size_t)h * RD * KD;
    float acc[4][4] = {};
    for (int kc = 0; kc < KD; kc += 16) {
        #pragma unroll
        for (int t = 0; t < 4; t++) {
            int e = tid + t * 256;
            int m = e >> 4, kk = e & 15;
            qws[kk][m] = qwp[(q0 + m) * KD + kc + kk];
            qrs[kk][m] = qrp[(q0 + m) * KD + kc + kk];
            ks [kk][m] = kp [(j0 + m) * KD + kc + kk];
        }
        for (int e = tid; e < 127 * 16; e += 256) {
            int bi = e >> 4, kk = e & 15;
            rks[kk][bi] = rkp[(size_t)(rbase + bi) * KD + kc + kk];
        }
        __syncthreads();
        #pragma unroll
        for (int kk = 0; kk < 16; kk++) {
            float aw[4], ar[4], bk[4], bb[7];
            #pragma unroll
            for (int i = 0; i < 4; i++) { aw[i] = qws[kk][ty * 4 + i]; ar[i] = qrs[kk][ty * 4 + i]; }
            #pragma unroll
            for (int j = 0; j < 4; j++) bk[j] = ks[kk][tx * 4 + j];
            int b0 = (tx - ty) * 4 + 60;
            #pragma unroll
            for (int o = 0; o < 7; o++) bb[o] = rks[kk][b0 + o];
            #pragma unroll
            for (int i = 0; i < 4; i++)
                #pragma unroll
                for (int j = 0; j < 4; j++)
                    acc[i][j] += aw[i] * bk[j] + ar[i] * bb[j - i + 3];
        }
        __syncthreads();
    }
    float* out = g_logits + (size_t)h * TT * TT;
    #pragma unroll
    for (int i = 0; i < 4; i++)
        #pragma unroll
        for (int j = 0; j < 4; j++)
            out[(size_t)(q0 + ty * 4 + i) * TT + j0 + tx * 4 + j] = acc[i][j];
}

// ---------------- row softmax, in place ----------------
__global__ void softmax_kernel() {
    __shared__ float s[256];
    int row = blockIdx.x;
    float* p = g_logits + (size_t)row * TT;
    int t = threadIdx.x;
    float v[6];
    float mx = -1e30f;
    #pragma unroll
    for (int i = 0; i < 6; i++) { v[i] = p[t + i * 256]; mx = fmaxf(mx, v[i]); }
    s[t] = mx; __syncthreads();
    for (int o = 128; o > 0; o >>= 1) { if (t < o) s[t] = fmaxf(s[t], s[t + o]); __syncthreads(); }
    mx = s[0]; __syncthreads();
    float sum = 0.f;
    #pragma unroll
    for (int i = 0; i < 6; i++) { v[i] = expf(v[i] - mx); sum += v[i]; }
    s[t] = sum; __syncthreads();
    for (int o = 128; o > 0; o >>= 1) { if (t < o) s[t] += s[t + o]; __syncthreads(); }
    float inv = 1.0f / s[0];
    #pragma unroll
    for (int i = 0; i < 6; i++) p[t + i * 256] = v[i] * inv;
}

// ---------------- launch ----------------
static float* dev_ptr(const void* symbol) {
    void* p = nullptr;
    cudaGetSymbolAddress(&p, symbol);
    return (float*)p;
}

extern "C" void kernel_launch(void* const* d_in, const int* in_sizes, int n_in,
                              void* d_out, int out_size) {
    const float* inputs = (const float*)d_in[0];
    const float* Wq  = (const float*)d_in[1];
    const float* Wk  = (const float*)d_in[2];
    const float* Wv  = (const float*)d_in[3];
    const float* Wrk = (const float*)d_in[4];
    const float* rwb = (const float*)d_in[5];
    const float* rrb = (const float*)d_in[6];
    const float* We  = (const float*)d_in[7];
    const float* be  = (const float*)d_in[8];
    float* out = (float*)d_out;

    float* p_posenc = dev_ptr(g_posenc);
    float* p_rk     = dev_ptr(g_rk);
    float* p_q      = dev_ptr(g_q);
    float* p_k      = dev_ptr(g_k);
    float* p_v      = dev_ptr(g_v);
    float* p_logits = dev_ptr(g_logits);
    float* p_attn   = dev_ptr(g_attn);

    dim3 blk(16, 16);

    // positional features
    pf_gamma_raw_kernel<<<(RD * NB + 255) / 256, 256>>>();
    pf_max_kernel<<<1, 1024>>>();
    pf_build_kernel<<<(RD * 96 + 255) / 256, 256>>>();

    // r_k = posenc @ Wrk  -> head-major [H,RD,KD]
    sgemm_kernel<<<dim3(512 / 64, (RD + 63) / 64, 1), blk>>>(
        p_posenc, 192, 0, Wrk, 512, 0, p_rk, 0, 0, RD, 512, 192, 1.0f, nullptr, KD);

    // q,k,v projections (head-major)
    sgemm_kernel<<<dim3(512 / 64, TT / 64, 1), blk>>>(
        inputs, CDIM, 0, Wq, 512, 0, p_q, 0, 0, TT, 512, CDIM, 0.125f, nullptr, KD);
    sgemm_kernel<<<dim3(512 / 64, TT / 64, 1), blk>>>(
        inputs, CDIM, 0, Wk, 512, 0, p_k, 0, 0, TT, 512, CDIM, 1.0f, nullptr, KD);
    sgemm_kernel<<<dim3(1536 / 64, TT / 64, 1), blk>>>(
        inputs, CDIM, 0, Wv, 1536, 0, p_v, 0, 0, TT, 1536, CDIM, 1.0f, nullptr, VD);

    // q + biases
    qbias_kernel<<<(HH * TT * KD + 255) / 256, 256>>>(rwb, rrb);

    // fused logits (content + shifted relative)
    logits_kernel<<<dim3(TT / 64, TT / 64, HH), blk>>>();

    // softmax
    softmax_kernel<<<HH * TT, 256>>>();

    // attn_out[t, h*VD+dv] = sum_j P[h,t,j] * v[h,j,dv]   (batched over heads)
    sgemm_kernel<<<dim3(VD / 64, TT / 64, HH), blk>>>(
        p_logits, TT, (size_t)TT * TT,
        p_v, VD, (size_t)TT * VD,
        p_attn, HH * VD, (size_t)VD,
        TT, VD, TT, 1.0f, nullptr, 0);

    // out = attn_out @ We + be
    sgemm_kernel<<<dim3(1536 / 64, TT / 64, 1), blk>>>(
        p_attn, HH * VD, 0, We, CDIM, 0, out, CDIM, 0, TT, CDIM, HH * VD, 1.0f, be, 0);
}

// round 4
// speedup vs baseline: 2.2280x; 2.2280x over previous
#include <cuda_runtime.h>
#include <cuda_bf16.h>
#include <math.h>
#include <stdint.h>

#define TT   1536
#define CDIM 1536
#define HH   8
#define KD   64
#define VD   192
#define RD   3071
#define RDP  3072
#define NB   32

typedef __nv_bfloat16 bf16;

// ========================= helpers =========================
__device__ __forceinline__ uint32_t smem_to_u32(const void* p) {
    uint32_t a;
    asm("{ .reg .u64 t; cvta.to.shared.u64 t, %1; cvt.u32.u64 %0, t; }" : "=r"(a) : "l"(p));
    return a;
}
#define CP_ASYNC16(dst, src) \
    asm volatile("cp.async.cg.shared.global [%0], [%1], 16;" :: "r"(dst), "l"(src))
#define CP_COMMIT() asm volatile("cp.async.commit_group;" ::: "memory")
#define CP_WAIT1()  asm volatile("cp.async.wait_group 1;" ::: "memory")

__device__ __forceinline__ void ldm_x4(uint32_t* r, uint32_t addr) {
    asm volatile("ldmatrix.sync.aligned.m8n8.x4.shared.b16 {%0,%1,%2,%3}, [%4];"
        : "=r"(r[0]), "=r"(r[1]), "=r"(r[2]), "=r"(r[3]) : "r"(addr));
}
__device__ __forceinline__ void mma_bf16(float* c, const uint32_t* a, const uint32_t* b) {
    asm volatile("mma.sync.aligned.m16n8k16.row.col.f32.bf16.bf16.f32 "
        "{%0,%1,%2,%3}, {%4,%5,%6,%7}, {%8,%9}, {%0,%1,%2,%3};"
        : "+f"(c[0]), "+f"(c[1]), "+f"(c[2]), "+f"(c[3])
        : "r"(a[0]), "r"(a[1]), "r"(a[2]), "r"(a[3]), "r"(b[0]), "r"(b[1]));
}

// ========================= scratch =========================
__device__ float g_gprobs[RD * NB];
__device__ float g_gmax;
__device__ __align__(16) bf16 g_pe_hi[RDP * 192], g_pe_lo[RDP * 192];
__device__ __align__(16) bf16 g_wqT_hi[512 * CDIM], g_wqT_lo[512 * CDIM];
__device__ __align__(16) bf16 g_wkT_hi[512 * CDIM], g_wkT_lo[512 * CDIM];
__device__ __align__(16) bf16 g_wvT_hi[CDIM * CDIM], g_wvT_lo[CDIM * CDIM];
__device__ __align__(16) bf16 g_weT_hi[CDIM * CDIM], g_weT_lo[CDIM * CDIM];
__device__ __align__(16) bf16 g_wrkT_hi[512 * 192], g_wrkT_lo[512 * 192];
__device__ __align__(16) bf16 g_in_hi[TT * CDIM], g_in_lo[TT * CDIM];
__device__ float g_q[HH * TT * KD];
__device__ float g_k[HH * TT * KD];
__device__ float g_v[HH * TT * VD];
__device__ float g_rkf[HH * RDP * KD];
__device__ __align__(16) bf16 g_qw_hi[HH * TT * KD], g_qw_lo[HH * TT * KD];
__device__ __align__(16) bf16 g_qr_hi[HH * TT * KD], g_qr_lo[HH * TT * KD];
__device__ __align__(16) bf16 g_k_hi[HH * TT * KD], g_k_lo[HH * TT * KD];
__device__ __align__(16) bf16 g_rk_hi[HH * RDP * KD], g_rk_lo[HH * RDP * KD];
__device__ __align__(16) bf16 g_vT_hi[HH * VD * TT], g_vT_lo[HH * VD * TT];
__device__ float g_content[(size_t)HH * TT * TT];
__device__ float g_rel[(size_t)HH * TT * RDP];
__device__ __align__(16) bf16 g_p_hi[(size_t)HH * TT * TT], g_p_lo[(size_t)HH * TT * TT];
__device__ float g_attn[TT * CDIM];
__device__ __align__(16) bf16 g_at_hi[TT * CDIM], g_at_lo[TT * CDIM];

__device__ __forceinline__ void split2(float x, bf16* hi, bf16* lo) {
    bf16 h = __float2bfloat16(x);
    *hi = h;
    *lo = __float2bfloat16(x - __bfloat162float(h));
}

// ========================= positional features =========================
__global__ void pf_gamma_raw_kernel() {
    int idx = blockIdx.x * blockDim.x + threadIdx.x;
    if (idx >= RD * NB) return;
    int r = idx / NB, i = idx % NB;
    double x    = fabs((double)(r - (TT - 1)));
    double mean = 48.0 * (i + 1);
    double conc = (mean / 24.0) * (mean / 24.0);
    double rate = mean / 576.0;
    double lu   = (conc - 1.0) * log(x) - rate * x;
    double ln   = lgamma(conc) - conc * log(rate);
    g_gprobs[idx] = (float)exp(lu - ln) + 1e-8f;
}

__global__ void pf_max_kernel() {
    __shared__ float s[1024];
    int t = threadIdx.x;
    float m = 0.f;
    for (int i = t; i < RD * NB; i += 1024) m = fmaxf(m, g_gprobs[i]);
    s[t] = m; __syncthreads();
    for (int o = 512; o > 0; o >>= 1) { if (t < o) s[t] = fmaxf(s[t], s[t + o]); __syncthreads(); }
    if (t == 0) g_gmax = s[0];
}

__global__ void pf_build_kernel() {
    int idx = blockIdx.x * blockDim.x + threadIdx.x;
    if (idx >= RDP * 96) return;
    int r = idx / 96, i = idx % 96;
    float v1 = 0.f, v2 = 0.f;
    if (r < RD) {
        float p  = (float)(r - (TT - 1));
        float ap = fabsf(p);
        float val;
        if (i < 32) {
            double mr = log(1536.0) / log(2.0);
            double hl = pow(2.0, 3.0 + (double)i * (mr - 3.0) / 31.0);
            val = expf(-(float)(0.6931471805599453 / hl) * ap);
        } else if (i < 64) {
            float cw = exp2f((float)(i - 32 + 1)) - 1.0f;
            val = (cw > ap) ? 1.0f : 0.0f;
        } else {
            val = g_gprobs[r * NB + (i - 64)] / g_gmax;
        }
        float sg = (p > 0.f) ? 1.f : ((p < 0.f) ? -1.f : 0.f);
        v1 = val; v2 = sg * val;
    }
    split2(v1, &g_pe_hi[r * 192 + i],      &g_pe_lo[r * 192 + i]);
    split2(v2, &g_pe_hi[r * 192 + 96 + i], &g_pe_lo[r * 192 + 96 + i]);
}

// ========================= split / transpose-split =========================
__global__ void split_kernel(const float* __restrict__ in, bf16* __restrict__ hi,
                             bf16* __restrict__ lo, int n) {
    int i = blockIdx.x * blockDim.x + threadIdx.x;
    if (i < n) split2(in[i], hi + i, lo + i);
}

__global__ void tsplit_kernel(const float* __restrict__ in, bf16* __restrict__ hi,
                              bf16* __restrict__ lo, int R, int Cc, size_t sIn, size_t sOut) {
    __shared__ float t[32][33];
    int z = blockIdx.z;
    in += (size_t)z * sIn;
    int c0 = blockIdx.x * 32, r0 = blockIdx.y * 32;
    int tx = threadIdx.x, ty = threadIdx.y;
    #pragma unroll
    for (int i = 0; i < 32; i += 8)
        t[ty + i][tx] = in[(size_t)(r0 + ty + i) * Cc + c0 + tx];
    __syncthreads();
    #pragma unroll
    for (int i = 0; i < 32; i += 8) {
        size_t o = (size_t)z * sOut + (size_t)(c0 + ty + i) * R + r0 + tx;
        split2(t[tx][ty + i], hi + o, lo + o);
    }
}

__global__ void qbias_split_kernel(const float* __restrict__ rwb, const float* __restrict__ rrb) {
    int idx = blockIdx.x * blockDim.x + threadIdx.x;
    if (idx >= HH * TT * KD) return;
    int h = idx / (TT * KD);
    int d = idx & (KD - 1);
    float q = g_q[idx];
    split2(q + rwb[h * KD + d], &g_qw_hi[idx], &g_qw_lo[idx]);
    split2(q + rrb[h * KD + d], &g_qr_hi[idx], &g_qr_lo[idx]);
}

// ========================= HMMA GEMM: C[M,N] = alpha * A[M,K] @ B[N,K]^T =========================
// hi/lo split bf16, 3-pass compensated. BM=128, BN=NT, BK=32, 8 warps (4x2).
template <int NT>
__global__ void __launch_bounds__(256)
mma_gemm(const bf16* __restrict__ Ahi, const bf16* __restrict__ Alo, size_t sA,
         const bf16* __restrict__ Bhi, const bf16* __restrict__ Blo, size_t sB,
         float* __restrict__ C, int ldc, size_t sC,
         int M, int Kt, float alpha, const float* __restrict__ bias, int hd, int reltile) {
    constexpr int AT = 128 * 64;       // bytes per A half-tile (128 rows x 64B)
    constexpr int BT = NT * 64;        // bytes per B half-tile
    constexpr int SS = 2 * AT + 2 * BT;
    constexpr int WN = NT / 2;         // n-columns per warp
    constexpr int NG = WN / 16;        // 16-wide n groups per warp
    extern __shared__ char smem[];
    const uint32_t sbase = smem_to_u32(smem);
    int tid = threadIdx.x, wid = tid >> 5, lane = tid & 31;
    int z = blockIdx.z;
    int m0 = blockIdx.y * 128;
    int n0 = reltile ? (11 - (int)blockIdx.y + (int)blockIdx.x) * 128 : blockIdx.x * NT;
    Ahi += (size_t)z * sA;  Alo += (size_t)z * sA;
    Bhi += (size_t)z * sB;  Blo += (size_t)z * sB;
    int mw = (wid & 3) * 32, nw = (wid >> 2) * WN;

    float acc[2][NG * 2][4];
    #pragma unroll
    for (int a = 0; a < 2; a++)
        #pragma unroll
        for (int b = 0; b < NG * 2; b++)
            #pragma unroll
            for (int c = 0; c < 4; c++) acc[a][b][c] = 0.f;

    int nblk = Kt >> 5;

    auto issue_stage = [&](int blk) {
        int k0 = blk * 32;
        uint32_t so = sbase + (blk & 1) * SS;
        #pragma unroll
        for (int i = tid; i < 128 * 4; i += 256) {
            int r = i >> 2, c = i & 3;
            uint32_t d = so + (((uint32_t)r << 2) + (uint32_t)(c ^ (r & 3))) * 16;
            const bf16* sh = Ahi + (size_t)(m0 + r) * Kt + k0 + c * 8;
            const bf16* sl = Alo + (size_t)(m0 + r) * Kt + k0 + c * 8;
            CP_ASYNC16(d, sh);
            CP_ASYNC16(d + AT, sl);
        }
        #pragma unroll
        for (int i = tid; i < NT * 4; i += 256) {
            int r = i >> 2, c = i & 3;
            uint32_t d = so + 2 * AT + (((uint32_t)r << 2) + (uint32_t)(c ^ (r & 3))) * 16;
            const bf16* sh = Bhi + (size_t)(n0 + r) * Kt + k0 + c * 8;
            const bf16* sl = Blo + (size_t)(n0 + r) * Kt + k0 + c * 8;
            CP_ASYNC16(d, sh);
            CP_ASYNC16(d + BT, sl);
        }
    };

    issue_stage(0);
    CP_COMMIT();
    for (int blk = 0; blk < nblk; blk++) {
        if (blk + 1 < nblk) issue_stage(blk + 1);
        CP_COMMIT();
        CP_WAIT1();
        __syncthreads();
        uint32_t so = sbase + (blk & 1) * SS;
        #pragma unroll
        for (int ks = 0; ks < 2; ks++) {
            uint32_t ah[8], al[8];
            #pragma unroll
            for (int fm = 0; fm < 2; fm++) {
                int ra = mw + fm * 16 + (lane & 15);
                int ca = ks * 2 + (lane >> 4);
                uint32_t off = (((uint32_t)ra << 2) + (uint32_t)(ca ^ (ra & 3))) * 16;
                ldm_x4(ah + fm * 4, so + off);
                ldm_x4(al + fm * 4, so + AT + off);
            }
            #pragma unroll
            for (int nt = 0; nt < NG; nt++) {
                int rb = nw + nt * 16 + ((lane >> 4) & 1) * 8 + (lane & 7);
                int cb = ks * 2 + ((lane >> 3) & 1);
                uint32_t offb = (((uint32_t)rb << 2) + (uint32_t)(cb ^ (rb & 3))) * 16;
                uint32_t bh[4], bl[4];
                ldm_x4(bh, so + 2 * AT + offb);
                ldm_x4(bl, so + 2 * AT + BT + offb);
                #pragma unroll
                for (int fm = 0; fm < 2; fm++) {
                    #pragma unroll
                    for (int hf = 0; hf < 2; hf++) {
                        float* cc = acc[fm][nt * 2 + hf];
                        mma_bf16(cc, ah + fm * 4, bh + hf * 2);
                        mma_bf16(cc, ah + fm * 4, bl + hf * 2);
                        mma_bf16(cc, al + fm * 4, bh + hf * 2);
                    }
                }
            }
        }
        __syncthreads();
    }

    // epilogue
    int g = lane >> 2, tg = lane & 3;
    #pragma unroll
    for (int fm = 0; fm < 2; fm++) {
        #pragma unroll
        for (int fn = 0; fn < NG * 2; fn++) {
            int n = n0 + nw + fn * 8 + tg * 2;
            int m = m0 + mw + fm * 16 + g;
            float* cc = acc[fm][fn];
            #pragma unroll
            for (int hrow = 0; hrow < 2; hrow++) {
                int mm = m + hrow * 8;
                #pragma unroll
                for (int jj = 0; jj < 2; jj++) {
                    int nn = n + jj;
                    float v = alpha * cc[hrow * 2 + jj];
                    if (bias) v += bias[nn];
                    size_t o;
                    if (hd) o = ((size_t)(nn / hd) * M + mm) * (size_t)hd + (nn % hd);
                    else    o = (size_t)z * sC + (size_t)mm * ldc + nn;
                    C[o] = v;
                }
            }
        }
    }
}

// ========================= combine + softmax + split-P =========================
__global__ void softmax_kernel() {
    __shared__ float s[256];
    int row = blockIdx.x;                 // h*T + q
    int q = row % TT;
    const float* cont = g_content + (size_t)row * TT;
    const float* rel  = g_rel + (size_t)row * RDP + (TT - 1 - q);
    bf16* phi = g_p_hi + (size_t)row * TT;
    bf16* plo = g_p_lo + (size_t)row * TT;
    int t = threadIdx.x;
    float v[6];
    float mx = -1e30f;
    #pragma unroll
    for (int i = 0; i < 6; i++) {
        int j = t + i * 256;
        v[i] = cont[j] + rel[j];
        mx = fmaxf(mx, v[i]);
    }
    s[t] = mx; __syncthreads();
    for (int o = 128; o > 0; o >>= 1) { if (t < o) s[t] = fmaxf(s[t], s[t + o]); __syncthreads(); }
    mx = s[0]; __syncthreads();
    float sum = 0.f;
    #pragma unroll
    for (int i = 0; i < 6; i++) { v[i] = expf(v[i] - mx); sum += v[i]; }
    s[t] = sum; __syncthreads();
    for (int o = 128; o > 0; o >>= 1) { if (t < o) s[t] += s[t + o]; __syncthreads(); }
    float inv = 1.0f / s[0];
    #pragma unroll
    for (int i = 0; i < 6; i++) {
        int j = t + i * 256;
        split2(v[i] * inv, phi + j, plo + j);
    }
}

// ========================= launch =========================
static void* dev_ptr(const void* symbol) {
    void* p = nullptr;
    cudaGetSymbolAddress(&p, symbol);
    return p;
}

extern "C" void kernel_launch(void* const* d_in, const int* in_sizes, int n_in,
                              void* d_out, int out_size) {
    const float* inputs = (const float*)d_in[0];
    const float* Wq  = (const float*)d_in[1];
    const float* Wk  = (const float*)d_in[2];
    const float* Wv  = (const float*)d_in[3];
    const float* Wrk = (const float*)d_in[4];
    const float* rwb = (const float*)d_in[5];
    const float* rrb = (const float*)d_in[6];
    const float* We  = (const float*)d_in[7];
    const float* be  = (const float*)d_in[8];
    float* out = (float*)d_out;

    const int SM128 = 2 * (2 * 128 * 64 + 2 * 128 * 64);  // 65536
    const int SM64  = 2 * (2 * 128 * 64 + 2 * 64 * 64);   // 49152
    cudaFuncSetAttribute(mma_gemm<128>, cudaFuncAttributeMaxDynamicSharedMemorySize, SM128);
    cudaFuncSetAttribute(mma_gemm<64>,  cudaFuncAttributeMaxDynamicSharedMemorySize, SM64);

    bf16* pe_hi = (bf16*)dev_ptr(g_pe_hi);   bf16* pe_lo = (bf16*)dev_ptr(g_pe_lo);
    bf16* wqT_hi = (bf16*)dev_ptr(g_wqT_hi); bf16* wqT_lo = (bf16*)dev_ptr(g_wqT_lo);
    bf16* wkT_hi = (bf16*)dev_ptr(g_wkT_hi); bf16* wkT_lo = (bf16*)dev_ptr(g_wkT_lo);
    bf16* wvT_hi = (bf16*)dev_ptr(g_wvT_hi); bf16* wvT_lo = (bf16*)dev_ptr(g_wvT_lo);
    bf16* weT_hi = (bf16*)dev_ptr(g_weT_hi); bf16* weT_lo = (bf16*)dev_ptr(g_weT_lo);
    bf16* wrkT_hi = (bf16*)dev_ptr(g_wrkT_hi); bf16* wrkT_lo = (bf16*)dev_ptr(g_wrkT_lo);
    bf16* in_hi = (bf16*)dev_ptr(g_in_hi);   bf16* in_lo = (bf16*)dev_ptr(g_in_lo);
    float* pq = (float*)dev_ptr(g_q);  float* pk = (float*)dev_ptr(g_k);
    float* pv = (float*)dev_ptr(g_v);  float* prkf = (float*)dev_ptr(g_rkf);
    bf16* qw_hi = (bf16*)dev_ptr(g_qw_hi); bf16* qw_lo = (bf16*)dev_ptr(g_qw_lo);
    bf16* qr_hi = (bf16*)dev_ptr(g_qr_hi); bf16* qr_lo = (bf16*)dev_ptr(g_qr_lo);
    bf16* k_hi = (bf16*)dev_ptr(g_k_hi);   bf16* k_lo = (bf16*)dev_ptr(g_k_lo);
    bf16* rk_hi = (bf16*)dev_ptr(g_rk_hi); bf16* rk_lo = (bf16*)dev_ptr(g_rk_lo);
    bf16* vT_hi = (bf16*)dev_ptr(g_vT_hi); bf16* vT_lo = (bf16*)dev_ptr(g_vT_lo);
    float* pcontent = (float*)dev_ptr(g_content);
    float* prel = (float*)dev_ptr(g_rel);
    bf16* p_hi = (bf16*)dev_ptr(g_p_hi); bf16* p_lo = (bf16*)dev_ptr(g_p_lo);
    float* pattn = (float*)dev_ptr(g_attn);
    bf16* at_hi = (bf16*)dev_ptr(g_at_hi); bf16* at_lo = (bf16*)dev_ptr(g_at_lo);

    // positional features -> split bf16 [3072,192] (row 3071 zero)
    pf_gamma_raw_kernel<<<(RD * NB + 255) / 256, 256>>>();
    pf_max_kernel<<<1, 1024>>>();
    pf_build_kernel<<<(RDP * 96 + 255) / 256, 256>>>();

    // split inputs; transpose-split weights
    split_kernel<<<(TT * CDIM + 255) / 256, 256>>>(inputs, in_hi, in_lo, TT * CDIM);
    dim3 tb(32, 8);
    tsplit_kernel<<<dim3(512 / 32, CDIM / 32, 1), tb>>>(Wq,  wqT_hi,  wqT_lo,  CDIM, 512, 0, 0);
    tsplit_kernel<<<dim3(512 / 32, CDIM / 32, 1), tb>>>(Wk,  wkT_hi,  wkT_lo,  CDIM, 512, 0, 0);
    tsplit_kernel<<<dim3(CDIM / 32, CDIM / 32, 1), tb>>>(Wv, wvT_hi,  wvT_lo,  CDIM, CDIM, 0, 0);
    tsplit_kernel<<<dim3(CDIM / 32, CDIM / 32, 1), tb>>>(We, weT_hi,  weT_lo,  CDIM, CDIM, 0, 0);
    tsplit_kernel<<<dim3(512 / 32, 192 / 32, 1), tb>>>(Wrk, wrkT_hi, wrkT_lo, 192, 512, 0, 0);

    // r_k projection: [3072,192] @ [512,192]^T -> head-major fp32 (K=192)
    mma_gemm<128><<<dim3(4, 24, 1), 256, SM128>>>(pe_hi, pe_lo, 0, wrkT_hi, wrkT_lo, 0,
        prkf, 0, 0, RDP, 192, 1.0f, nullptr, KD, 0);
    // q,k,v projections -> head-major fp32 (K=1536)
    mma_gemm<128><<<dim3(4, 12, 1), 256, SM128>>>(in_hi, in_lo, 0, wqT_hi, wqT_lo, 0,
        pq, 0, 0, TT, CDIM, 0.125f, nullptr, KD, 0);
    mma_gemm<128><<<dim3(4, 12, 1), 256, SM128>>>(in_hi, in_lo, 0, wkT_hi, wkT_lo, 0,
        pk, 0, 0, TT, CDIM, 1.0f, nullptr, KD, 0);
    mma_gemm<128><<<dim3(12, 12, 1), 256, SM128>>>(in_hi, in_lo, 0, wvT_hi, wvT_lo, 0,
        pv, 0, 0, TT, CDIM, 1.0f, nullptr, VD, 0);

    // splits for the attention GEMMs
    qbias_split_kernel<<<(HH * TT * KD + 255) / 256, 256>>>(rwb, rrb);
    split_kernel<<<(HH * TT * KD + 255) / 256, 256>>>(pk, k_hi, k_lo, HH * TT * KD);
    split_kernel<<<(HH * RDP * KD + 255) / 256, 256>>>(prkf, rk_hi, rk_lo, HH * RDP * KD);
    tsplit_kernel<<<dim3(VD / 32, TT / 32, HH), tb>>>(pv, vT_hi, vT_lo, TT, VD,
        (size_t)TT * VD, (size_t)VD * TT);

    // content logits: per head [1536,64] @ [1536,64]^T  (K=64)
    mma_gemm<128><<<dim3(12, 12, HH), 256, SM128>>>(qw_hi, qw_lo, (size_t)TT * KD,
        k_hi, k_lo, (size_t)TT * KD, pcontent, TT, (size_t)TT * TT, TT, KD, 1.0f, nullptr, 0, 0);
    // banded relative logits: per head [1536,64] @ [3072,64]^T, 13 diagonal N-tiles
    mma_gemm<128><<<dim3(13, 12, HH), 256, SM128>>>(qr_hi, qr_lo, (size_t)TT * KD,
        rk_hi, rk_lo, (size_t)RDP * KD, prel, RDP, (size_t)TT * RDP, TT, KD, 1.0f, nullptr, 0, 1);

    // combine + softmax -> P (bf16 hi/lo)
    softmax_kernel<<<HH * TT, 256>>>();

    // P @ V: per head [1536,1536] @ [192,1536]^T -> attn[1536, h*192+..]  (K=1536)
    mma_gemm<64><<<dim3(3, 12, HH), 256, SM64>>>(p_hi, p_lo, (size_t)TT * TT,
        vT_hi, vT_lo, (size_t)VD * TT, pattn, CDIM, (size_t)VD, TT, TT, 1.0f, nullptr, 0, 0);

    // split attn; out = attn @ We + be  (K=1536)
    split_kernel<<<(TT * CDIM + 255) / 256, 256>>>(pattn, at_hi, at_lo, TT * CDIM);
    mma_gemm<128><<<dim3(12, 12, 1), 256, SM128>>>(at_hi, at_lo, 0, weT_hi, weT_lo, 0,
        out, CDIM, 0, TT, CDIM, 1.0f, be, 0, 0);
}